// round 15
// baseline (speedup 1.0000x reference)
#include <cuda_runtime.h>
#include <cuda_bf16.h>
#include <cuda_fp16.h>
#include <cstdint>
#include <cstddef>

#define NN 8192
#define IND 256
#define OD 128
#define SPLITS 4
#define JSPAN (NN / SPLITS)      // 2048
#define KT 64                    // j per tile
#define TILES (JSPAN / KT)       // 32

// smem byte offsets (main kernel)
#define AH_OFF 0                 // P [2 buf][128 i][64 j] fp16 : 2 x 16 KB
#define BH_OFF 32768             // V [2 buf][128 f][64 j] fp16 : 2 x 16 KB
#define EJ_OFF 65536             // float2[2048] : 16 KB
#define DR_OFF 81920             // 256 floats (den reduce)
#define SMEM_USED (81920 + 1024)
#define SMEM_DYN (SMEM_USED + 1024)   // + alignment pad

// ---------------- device scratch ----------------
__device__ float g_WT[256 * 256];
__device__ float g_T[NN * 256];
__device__ float g_EI2[NN * 2];          // exp(0.2 s)
__device__ float g_EI8[NN * 2];          // exp(0.8 s)
__device__ float2 g_EJ[NN * 2];          // (exp(0.2 d), exp(0.8 d))
__device__ __half g_VThi[2 * 128 * NN];
__device__ uint32_t g_adjbits[(size_t)NN * (NN / 32)];   // 8 MB
__device__ float g_num[(size_t)SPLITS * NN * 2 * 128];   // 32 MB
__device__ float g_den[SPLITS * NN * 2];

// ---------------- helpers ----------------
__device__ __forceinline__ uint32_t smem_u32(const void* p) {
    uint32_t a;
    asm("{ .reg .u64 t; cvta.to.shared.u64 t, %1; cvt.u32.u64 %0, t; }" : "=r"(a) : "l"(p));
    return a;
}
__device__ __forceinline__ uint32_t swz(uint32_t x) { return x ^ ((x >> 3) & 0x70); }

__device__ __forceinline__ void ldmx4(uint32_t* r, uint32_t addr) {
    asm volatile("ldmatrix.sync.aligned.m8n8.x4.shared.b16 {%0,%1,%2,%3}, [%4];"
                 : "=r"(r[0]), "=r"(r[1]), "=r"(r[2]), "=r"(r[3]) : "r"(addr));
}
__device__ __forceinline__ void mma16816(float* c, const uint32_t* a, const uint32_t* b) {
    asm volatile("mma.sync.aligned.m16n8k16.row.col.f32.f16.f16.f32 "
                 "{%0,%1,%2,%3}, {%4,%5,%6,%7}, {%8,%9}, {%0,%1,%2,%3};"
                 : "+f"(c[0]), "+f"(c[1]), "+f"(c[2]), "+f"(c[3])
                 : "r"(a[0]), "r"(a[1]), "r"(a[2]), "r"(a[3]), "r"(b[0]), "r"(b[1]));
}

// ---------------- kernel 0: transpose W ----------------
__global__ void k_transpose_w(const float* __restrict__ W) {
    int idx = blockIdx.x * 256 + threadIdx.x;
    int k = idx >> 8, o = idx & 255;
    g_WT[k * 256 + o] = W[o * 256 + k];
}

// ---------------- kernel 1: T = X @ W^T ----------------
__global__ __launch_bounds__(256, 2) void k_gemm_t(const float* __restrict__ X) {
    __shared__ float As[32][36];
    __shared__ float4 Bs4[32 * 64];
    int tid = threadIdx.x;
    int iBase = blockIdx.x << 5;
    int rb = (tid >> 5) << 2;
    int cq = (tid & 31) << 1;
    float acc[32];
#pragma unroll
    for (int i = 0; i < 32; i++) acc[i] = 0.f;
    const float4* X4 = (const float4*)X;
    const float4* WT4 = (const float4*)g_WT;
    int ii = tid >> 3, kg = tid & 7;
    for (int kb = 0; kb < IND; kb += 32) {
        float4 xv = X4[(size_t)(iBase + ii) * 64 + (kb >> 2) + kg];
        As[kg * 4 + 0][ii] = xv.x; As[kg * 4 + 1][ii] = xv.y;
        As[kg * 4 + 2][ii] = xv.z; As[kg * 4 + 3][ii] = xv.w;
#pragma unroll
        for (int r = 0; r < 8; r++)
            Bs4[tid + (r << 8)] = WT4[(kb << 6) + tid + (r << 8)];
        __syncthreads();
#pragma unroll
        for (int k = 0; k < 32; k++) {
            float4 a = *(const float4*)&As[k][rb];
            float4 b0 = Bs4[(k << 6) + cq];
            float4 b1 = Bs4[(k << 6) + cq + 1];
#define FMA8T(r, av) \
            acc[(r)*8+0] += (av)*b0.x; acc[(r)*8+1] += (av)*b0.y; \
            acc[(r)*8+2] += (av)*b0.z; acc[(r)*8+3] += (av)*b0.w; \
            acc[(r)*8+4] += (av)*b1.x; acc[(r)*8+5] += (av)*b1.y; \
            acc[(r)*8+6] += (av)*b1.z; acc[(r)*8+7] += (av)*b1.w;
            FMA8T(0, a.x) FMA8T(1, a.y) FMA8T(2, a.z) FMA8T(3, a.w)
        }
        __syncthreads();
    }
    float4* T4 = (float4*)g_T;
#pragma unroll
    for (int r = 0; r < 4; r++) {
        T4[(size_t)(iBase + rb + r) * 64 + cq] =
            make_float4(acc[r * 8 + 0], acc[r * 8 + 1], acc[r * 8 + 2], acc[r * 8 + 3]);
        T4[(size_t)(iBase + rb + r) * 64 + cq + 1] =
            make_float4(acc[r * 8 + 4], acc[r * 8 + 5], acc[r * 8 + 6], acc[r * 8 + 7]);
    }
}

// ---------------- kernel 2: scores + exps ----------------
__global__ void k_scores(const float* __restrict__ asrc, const float* __restrict__ adst) {
    int warp = blockIdx.x * 8 + (threadIdx.x >> 5);
    int lane = threadIdx.x & 31;
    const float4* T4 = (const float4*)g_T;
    const float4* A4 = (const float4*)asrc;
    const float4* B4 = (const float4*)adst;
    float4 t0 = T4[(size_t)warp * 64 + lane];
    float4 t1 = T4[(size_t)warp * 64 + 32 + lane];
    float4 a0 = A4[lane], a1 = A4[32 + lane];
    float4 d0v = B4[lane], d1v = B4[32 + lane];
    float s0 = t0.x * a0.x + t0.y * a0.y + t0.z * a0.z + t0.w * a0.w;
    float s1 = t1.x * a1.x + t1.y * a1.y + t1.z * a1.z + t1.w * a1.w;
    float d0 = t0.x * d0v.x + t0.y * d0v.y + t0.z * d0v.z + t0.w * d0v.w;
    float d1 = t1.x * d1v.x + t1.y * d1v.y + t1.z * d1v.z + t1.w * d1v.w;
#pragma unroll
    for (int off = 16; off; off >>= 1) {
        s0 += __shfl_xor_sync(0xFFFFFFFFu, s0, off);
        s1 += __shfl_xor_sync(0xFFFFFFFFu, s1, off);
        d0 += __shfl_xor_sync(0xFFFFFFFFu, d0, off);
        d1 += __shfl_xor_sync(0xFFFFFFFFu, d1, off);
    }
    if (lane == 0) {
        g_EI2[warp * 2 + 0] = __expf(0.2f * s0);
        g_EI2[warp * 2 + 1] = __expf(0.2f * s1);
        g_EI8[warp * 2 + 0] = __expf(0.8f * s0);
        g_EI8[warp * 2 + 1] = __expf(0.8f * s1);
        g_EJ[warp * 2 + 0] = make_float2(__expf(0.2f * d0), __expf(0.8f * d0));
        g_EJ[warp * 2 + 1] = make_float2(__expf(0.2f * d1), __expf(0.8f * d1));
    }
}

// ---------------- kernel 3: VT = T^T in fp16 ----------------
__global__ void k_vt() {
    __shared__ float ts[32][33];
    int h = blockIdx.z, fb = blockIdx.y << 5, jt = blockIdx.x << 5;
    int tx = threadIdx.x & 31, ty = threadIdx.x >> 5;
#pragma unroll
    for (int k = 0; k < 4; k++) {
        int j = jt + ty + k * 8;
        ts[ty + k * 8][tx] = g_T[(size_t)j * 256 + h * 128 + fb + tx];
    }
    __syncthreads();
#pragma unroll
    for (int k = 0; k < 4; k++) {
        int f = fb + ty + k * 8;
        float v = ts[tx][ty + k * 8];
        size_t o = ((size_t)(h * 128 + f) << 13) + jt + tx;
        g_VThi[o] = __float2half_rn(v);
    }
}

// ---------------- kernel 4: adjacency -> bitmask ----------------
__global__ void k_adjbits(const int* __restrict__ adj) {
    int row = blockIdx.x, tid = threadIdx.x;
    const int4* a4 = (const int4*)(adj + (size_t)row * NN + tid * 32);
    uint32_t w = 0;
#pragma unroll
    for (int q = 0; q < 8; q++) {
        int4 v = a4[q];
        w |= (v.x != 0 ? 1u : 0u) << (q * 4 + 0);
        w |= (v.y != 0 ? 1u : 0u) << (q * 4 + 1);
        w |= (v.z != 0 ? 1u : 0u) << (q * 4 + 2);
        w |= (v.w != 0 ? 1u : 0u) << (q * 4 + 3);
    }
    g_adjbits[(size_t)row * 256 + tid] = w;
}

// ---------------- kernel 5: main — pipelined P-build + HMMA, split-K (R10 body, SPLITS=4) ----------------
// grid: (SPLITS, 2 heads, 64 i-tiles); block 256 = 8 warps (4 M x 2 N); 2 CTAs/SM
__global__ __launch_bounds__(256, 2) void k_gat_mma() {
    extern __shared__ char dsm[];
    uint32_t sb_raw = smem_u32(dsm);
    uint32_t sb = (sb_raw + 1023) & ~1023u;
    char* sp = dsm + (sb - sb_raw);

    int tid = threadIdx.x;
    int lane = tid & 31, wid = tid >> 5;
    int split = blockIdx.x, h = blockIdx.y, iTile = blockIdx.z;
    int iBase = iTile << 7;
    int jBase = split * JSPAN;

    // builder identity
    int bi = tid & 127, half = tid >> 7;
    int gi0 = (iBase + bi) * 2 + h;
    float e2i = g_EI2[gi0], e8i = g_EI8[gi0];
    float den = 0.f;
    int mrot = (bi >> 3) & 3;
    uint32_t pco = (uint32_t)(bi * 128 + half * 64);     // P row base (bytes)
    size_t arow = (size_t)(iBase + bi) * 256 + half;

    // V loader identity (4 float4 per thread per tile)
    int frow0 = tid >> 3, ch0 = tid & 7;                 // + c*32 rows per c

    // mma identity
    int wm = wid >> 1, wn = wid & 1;
    uint32_t aRow = (uint32_t)((wm * 32 + (lane & 15)) * 128 + (lane >> 4) * 16);
    uint32_t bRow = (uint32_t)((wn * 64 + ((lane >> 4) & 1) * 8 + (lane & 7)) * 128 +
                               ((lane >> 3) & 1) * 16);

    float acc[2][8][4];
#pragma unroll
    for (int a = 0; a < 2; a++)
#pragma unroll
        for (int b = 0; b < 8; b++)
#pragma unroll
            for (int c = 0; c < 4; c++) acc[a][b][c] = 0.f;

    float2* ejs = (float2*)(sp + EJ_OFF);
    float* dred = (float*)(sp + DR_OFF);
    const float4* vhi4 = (const float4*)g_VThi;

    // ---- prologue ----
    // EJ table for the whole split (2048 float2)
#pragma unroll
    for (int r = 0; r < 8; r++) {
        int u = tid + (r << 8);
        ejs[u] = g_EJ[(jBase + u) * 2 + h];
    }
    // V tile 0 direct to buf 0
#pragma unroll
    for (int c = 0; c < 4; c++) {
        int frow = frow0 + c * 32;
        int gidx = (h * 128 + frow) * 1024 + (jBase >> 3) + ch0;
        *(float4*)(sp + BH_OFF + swz((uint32_t)(frow * 128 + ch0 * 16))) = vhi4[gidx];
    }
    uint32_t word0 = g_adjbits[arow + ((uint32_t)jBase >> 5)];
    __syncthreads();   // EJ ready

    // build P tile 0 into buf 0
#pragma unroll
    for (int mm = 0; mm < 16; mm++) {
        int m = (mm + mrot * 4) & 15;
        int jj = half * 32 + 2 * m;
        float4 ev = *(const float4*)&ejs[jj];        // (e2x, e8x, e2y, e8y)
        float w0 = (e2i * ev.x) * fmaxf(e8i * ev.y, 1.f);
        float w1 = (e2i * ev.z) * fmaxf(e8i * ev.w, 1.f);
        w0 = ((word0 >> (2 * m)) & 1u) ? w0 : 0.f;
        w1 = ((word0 >> (2 * m + 1)) & 1u) ? w1 : 0.f;
        den += w0 + w1;
        *(__half2*)(sp + AH_OFF + swz(pco + 4 * m)) = __floats2half2_rn(w0, w1);
    }
    __syncthreads();   // P0 + V0 ready

    // ---- main loop: 1 barrier per tile ----
    for (int t = 0; t < TILES; t++) {
        uint32_t bb = (uint32_t)(t & 1) << 14;      // 16384-byte buffer stride
        uint32_t bn = bb ^ 16384u;

        // early: issue V(t+1) loads into regs + adjacency word
        float4 vr[4];
        uint32_t word;
        if (t + 1 < TILES) {
            int jt1 = jBase + (t + 1) * KT;
#pragma unroll
            for (int c = 0; c < 4; c++) {
                int frow = frow0 + c * 32;
                vr[c] = vhi4[(h * 128 + frow) * 1024 + (jt1 >> 3) + ch0];
            }
            word = g_adjbits[arow + ((uint32_t)jt1 >> 5)];
        }

        // MMA(t) from buffer bb
#pragma unroll
        for (int ks = 0; ks < 4; ks++) {
            uint32_t ah[2][4];
#pragma unroll
            for (int mi = 0; mi < 2; mi++)
                ldmx4(ah[mi], sb + AH_OFF + bb + swz(aRow + mi * 2048 + ks * 32));
#pragma unroll
            for (int nb = 0; nb < 4; nb++) {
                uint32_t bh4[4];
                ldmx4(bh4, sb + BH_OFF + bb + swz(bRow + nb * 2048 + ks * 32));
#pragma unroll
                for (int mi = 0; mi < 2; mi++) {
                    mma16816(acc[mi][2 * nb + 0], ah[mi], &bh4[0]);
                    mma16816(acc[mi][2 * nb + 1], ah[mi], &bh4[2]);
                }
            }
        }

        // produce tile t+1 into buffer bn
        if (t + 1 < TILES) {
            int ej0 = (t + 1) * KT + half * 32;
#pragma unroll
            for (int mm = 0; mm < 16; mm++) {
                int m = (mm + mrot * 4) & 15;
                float4 ev = *(const float4*)&ejs[ej0 + 2 * m];
                float w0 = (e2i * ev.x) * fmaxf(e8i * ev.y, 1.f);
                float w1 = (e2i * ev.z) * fmaxf(e8i * ev.w, 1.f);
                w0 = ((word >> (2 * m)) & 1u) ? w0 : 0.f;
                w1 = ((word >> (2 * m + 1)) & 1u) ? w1 : 0.f;
                den += w0 + w1;
                *(__half2*)(sp + AH_OFF + bn + swz(pco + 4 * m)) = __floats2half2_rn(w0, w1);
            }
#pragma unroll
            for (int c = 0; c < 4; c++) {
                int frow = frow0 + c * 32;
                *(float4*)(sp + BH_OFF + bn + swz((uint32_t)(frow * 128 + ch0 * 16))) = vr[c];
            }
        }
        __syncthreads();
    }

    // denominator reduce + store
    dred[tid] = den;
    __syncthreads();
    if (tid < 128)
        g_den[((size_t)split * NN + iBase + tid) * 2 + h] = dred[tid] + dred[tid + 128];

    // numerator stores
#pragma unroll
    for (int mi = 0; mi < 2; mi++)
#pragma unroll
        for (int nb8 = 0; nb8 < 8; nb8++) {
            int i0 = iBase + wm * 32 + mi * 16 + (lane >> 2);
            int f0 = wn * 64 + nb8 * 8 + (lane & 3) * 2;
            size_t b0 = ((size_t)(split * NN + i0) * 2 + h) * 128 + f0;
            *(float2*)&g_num[b0] = make_float2(acc[mi][nb8][0], acc[mi][nb8][1]);
            *(float2*)&g_num[b0 + 2048] = make_float2(acc[mi][nb8][2], acc[mi][nb8][3]);
        }
}

// ---------------- kernel 6: combine splits + normalize + head mean ----------------
__global__ void k_combine(float* __restrict__ out) {
    int idx = blockIdx.x * 256 + threadIdx.x;   // 1M
    int i = idx >> 7, f = idx & 127;
    float r = 0.f;
#pragma unroll
    for (int h = 0; h < 2; h++) {
        float n = 0.f, d = 0.f;
#pragma unroll
        for (int s = 0; s < SPLITS; s++) {
            n += g_num[(((size_t)s * NN + i) * 2 + h) * 128 + f];
            d += g_den[((size_t)s * NN + i) * 2 + h];
        }
        r += (d > 0.f) ? n / d : 0.f;
    }
    out[idx] = 0.5f * r;
}

// ---------------- launch ----------------
extern "C" void kernel_launch(void* const* d_in, const int* in_sizes, int n_in,
                              void* d_out, int out_size) {
    const float* features = (const float*)d_in[0];
    const int*   adjacency = (const int*)d_in[1];
    const float* W = (const float*)d_in[2];
    const float* attn_src = (const float*)d_in[3];
    const float* attn_dst = (const float*)d_in[4];
    float* out = (float*)d_out;

    cudaFuncSetAttribute(k_gat_mma, cudaFuncAttributeMaxDynamicSharedMemorySize, SMEM_DYN);

    k_transpose_w<<<256, 256>>>(W);
    k_gemm_t<<<NN / 32, 256>>>(features);
    k_scores<<<NN / 8, 256>>>(attn_src, attn_dst);
    k_vt<<<dim3(NN / 32, 4, 2), 256>>>();
    k_adjbits<<<NN, 256>>>(adjacency);
    k_gat_mma<<<dim3(SPLITS, 2, 64), 256, SMEM_DYN>>>();
    k_combine<<<NN * OD / 256, 256>>>(out);
}

// round 16
// speedup vs baseline: 1.0428x; 1.0428x over previous
#include <cuda_runtime.h>
#include <cuda_bf16.h>
#include <cuda_fp16.h>
#include <cstdint>
#include <cstddef>

#define NN 8192
#define IND 256
#define OD 128
#define SPLITS 4
#define JSPAN (NN / SPLITS)      // 2048
#define KT 64                    // j per tile
#define TILES (JSPAN / KT)       // 32

// smem byte offsets (main kernel)
#define AH_OFF 0                 // P [2 buf][128 i][64 j] fp16 : 2 x 16 KB
#define BH_OFF 32768             // V [2 buf][128 f][64 j] fp16 : 2 x 16 KB
#define EJ_OFF 65536             // float2[2048] : 16 KB
#define DR_OFF 81920             // 256 floats (den reduce)
#define SMEM_USED (81920 + 1024)
#define SMEM_DYN (SMEM_USED + 1024)   // + alignment pad

// ---------------- device scratch ----------------
__device__ float g_U[4 * 256];           // u vectors: [src h0, src h1, dst h0, dst h1]
__device__ __half g_Xh[NN * IND];        // X in fp16
__device__ __half g_Wh[256 * 256];       // W in fp16
__device__ __half g_Th[NN * 256];        // T in fp16 (row-major)
__device__ float g_EI2[NN * 2];          // exp(0.2 s)
__device__ float g_EI8[NN * 2];          // exp(0.8 s)
__device__ float2 g_EJ[NN * 2];          // (exp(0.2 d), exp(0.8 d))
__device__ __half g_VThi[2 * 128 * NN];
__device__ uint32_t g_adjbits[(size_t)NN * (NN / 32)];   // 8 MB
__device__ float g_num[(size_t)SPLITS * NN * 2 * 128];   // 32 MB
__device__ float g_den[SPLITS * NN * 2];

// ---------------- helpers ----------------
__device__ __forceinline__ uint32_t smem_u32(const void* p) {
    uint32_t a;
    asm("{ .reg .u64 t; cvta.to.shared.u64 t, %1; cvt.u32.u64 %0, t; }" : "=r"(a) : "l"(p));
    return a;
}
__device__ __forceinline__ uint32_t swz(uint32_t x) { return x ^ ((x >> 3) & 0x70); }

__device__ __forceinline__ void ldmx4(uint32_t* r, uint32_t addr) {
    asm volatile("ldmatrix.sync.aligned.m8n8.x4.shared.b16 {%0,%1,%2,%3}, [%4];"
                 : "=r"(r[0]), "=r"(r[1]), "=r"(r[2]), "=r"(r[3]) : "r"(addr));
}
__device__ __forceinline__ void mma16816(float* c, const uint32_t* a, const uint32_t* b) {
    asm volatile("mma.sync.aligned.m16n8k16.row.col.f32.f16.f16.f32 "
                 "{%0,%1,%2,%3}, {%4,%5,%6,%7}, {%8,%9}, {%0,%1,%2,%3};"
                 : "+f"(c[0]), "+f"(c[1]), "+f"(c[2]), "+f"(c[3])
                 : "r"(a[0]), "r"(a[1]), "r"(a[2]), "r"(a[3]), "r"(b[0]), "r"(b[1]));
}

// ---------------- kernel 0a: u = attn @ W (per head, src/dst), fp32 exact ----------------
__global__ void k_prep(const float* __restrict__ W,
                       const float* __restrict__ asrc, const float* __restrict__ adst) {
    __shared__ float sa[256], sd[256];
    int k = threadIdx.x;
    sa[k] = asrc[k]; sd[k] = adst[k];
    __syncthreads();
    float us0 = 0.f, us1 = 0.f, ud0 = 0.f, ud1 = 0.f;
#pragma unroll 4
    for (int o = 0; o < 128; o++) {
        float w0 = W[o * 256 + k];
        float w1 = W[(128 + o) * 256 + k];
        us0 += sa[o] * w0;       ud0 += sd[o] * w0;
        us1 += sa[128 + o] * w1; ud1 += sd[128 + o] * w1;
    }
    g_U[0 * 256 + k] = us0; g_U[1 * 256 + k] = us1;
    g_U[2 * 256 + k] = ud0; g_U[3 * 256 + k] = ud1;
}

// ---------------- kernel 0b: W -> fp16 ----------------
__global__ void k_wh(const float* __restrict__ W) {
    int idx = blockIdx.x * 256 + threadIdx.x;    // 16384 float4
    float4 v = ((const float4*)W)[idx];
    __half2 a = __floats2half2_rn(v.x, v.y), b = __floats2half2_rn(v.z, v.w);
    ((uint2*)g_Wh)[idx] = make_uint2(*(uint32_t*)&a, *(uint32_t*)&b);
}

// ---------------- kernel 0c: X -> fp16 ----------------
__global__ void k_xh(const float* __restrict__ X) {
    int idx = blockIdx.x * 256 + threadIdx.x;    // 524288 float4
    float4 v = ((const float4*)X)[idx];
    __half2 a = __floats2half2_rn(v.x, v.y), b = __floats2half2_rn(v.z, v.w);
    ((uint2*)g_Xh)[idx] = make_uint2(*(uint32_t*)&a, *(uint32_t*)&b);
}

// ---------------- kernel 1: scores from X (exact fp32) + exps ----------------
__global__ void k_scores_x(const float* __restrict__ X) {
    __shared__ float4 su[256];                   // 4 u vectors x 64 float4
    int tid = threadIdx.x;
    su[tid] = ((const float4*)g_U)[tid];
    __syncthreads();
    int warp = blockIdx.x * 8 + (tid >> 5);
    int lane = tid & 31;
    const float4* X4 = (const float4*)X;
    float4 x0 = X4[(size_t)warp * 64 + lane * 2];
    float4 x1 = X4[(size_t)warp * 64 + lane * 2 + 1];
    float r[4];
#pragma unroll
    for (int v = 0; v < 4; v++) {
        float4 u0 = su[v * 64 + lane * 2];
        float4 u1 = su[v * 64 + lane * 2 + 1];
        r[v] = x0.x * u0.x + x0.y * u0.y + x0.z * u0.z + x0.w * u0.w +
               x1.x * u1.x + x1.y * u1.y + x1.z * u1.z + x1.w * u1.w;
    }
#pragma unroll
    for (int off = 16; off; off >>= 1)
#pragma unroll
        for (int v = 0; v < 4; v++)
            r[v] += __shfl_xor_sync(0xFFFFFFFFu, r[v], off);
    if (lane == 0) {
        // r[0]=s h0, r[1]=s h1, r[2]=d h0, r[3]=d h1
        g_EI2[warp * 2 + 0] = __expf(0.2f * r[0]);
        g_EI2[warp * 2 + 1] = __expf(0.2f * r[1]);
        g_EI8[warp * 2 + 0] = __expf(0.8f * r[0]);
        g_EI8[warp * 2 + 1] = __expf(0.8f * r[1]);
        g_EJ[warp * 2 + 0] = make_float2(__expf(0.2f * r[2]), __expf(0.8f * r[2]));
        g_EJ[warp * 2 + 1] = make_float2(__expf(0.2f * r[3]), __expf(0.8f * r[3]));
    }
}

// ---------------- kernel 2: T = X @ W^T via HMMA (fp16 in, fp16 out) ----------------
// grid (64 mTiles, 2 nTiles); block 256 = 8 warps (4 M x 2 N); tile 128m x 128n, K loop 4x64
__global__ __launch_bounds__(256, 2) void k_gemm_h() {
    __shared__ __half At[128 * 64];              // 16 KB, SW128 rows of 128B
    __shared__ __half Bt[128 * 64];              // 16 KB
    uint32_t sbA = smem_u32(At), sbB = smem_u32(Bt);

    int tid = threadIdx.x;
    int lane = tid & 31, wid = tid >> 5;
    int mBase = blockIdx.x << 7, nBase = blockIdx.y << 7;

    int frow0 = tid >> 3, ch0 = tid & 7;         // loader: rows {r, r+32, r+64, r+96}
    int wm = wid >> 1, wn = wid & 1;
    uint32_t aRow = (uint32_t)((wm * 32 + (lane & 15)) * 128 + (lane >> 4) * 16);
    uint32_t bRow = (uint32_t)((wn * 64 + ((lane >> 4) & 1) * 8 + (lane & 7)) * 128 +
                               ((lane >> 3) & 1) * 16);

    float acc[2][8][4];
#pragma unroll
    for (int a = 0; a < 2; a++)
#pragma unroll
        for (int b = 0; b < 8; b++)
#pragma unroll
            for (int c = 0; c < 4; c++) acc[a][b][c] = 0.f;

    const float4* X4 = (const float4*)g_Xh;      // row stride 32 float4 (256 halves)
    const float4* W4 = (const float4*)g_Wh;

    for (int kt = 0; kt < 4; kt++) {
        int kq = kt * 8;                         // float4 offset within row
#pragma unroll
        for (int c = 0; c < 4; c++) {
            int frow = frow0 + c * 32;
            uint32_t so = swz((uint32_t)(frow * 128 + ch0 * 16));
            *(float4*)((char*)At + so) = X4[(size_t)(mBase + frow) * 32 + kq + ch0];
            *(float4*)((char*)Bt + so) = W4[(size_t)(nBase + frow) * 32 + kq + ch0];
        }
        __syncthreads();
#pragma unroll
        for (int ks = 0; ks < 4; ks++) {
            uint32_t ah[2][4];
#pragma unroll
            for (int mi = 0; mi < 2; mi++)
                ldmx4(ah[mi], sbA + swz(aRow + mi * 2048 + ks * 32));
#pragma unroll
            for (int nb = 0; nb < 4; nb++) {
                uint32_t bh4[4];
                ldmx4(bh4, sbB + swz(bRow + nb * 2048 + ks * 32));
#pragma unroll
                for (int mi = 0; mi < 2; mi++) {
                    mma16816(acc[mi][2 * nb + 0], ah[mi], &bh4[0]);
                    mma16816(acc[mi][2 * nb + 1], ah[mi], &bh4[2]);
                }
            }
        }
        __syncthreads();
    }

    // epilogue: fp16 stores to g_Th row-major
#pragma unroll
    for (int mi = 0; mi < 2; mi++)
#pragma unroll
        for (int nb8 = 0; nb8 < 8; nb8++) {
            int i0 = mBase + wm * 32 + mi * 16 + (lane >> 2);
            int f0 = nBase + wn * 64 + nb8 * 8 + (lane & 3) * 2;
            __half2 lo = __floats2half2_rn(acc[mi][nb8][0], acc[mi][nb8][1]);
            __half2 hi = __floats2half2_rn(acc[mi][nb8][2], acc[mi][nb8][3]);
            *(__half2*)&g_Th[(size_t)i0 * 256 + f0] = lo;
            *(__half2*)&g_Th[(size_t)(i0 + 8) * 256 + f0] = hi;
        }
}

// ---------------- kernel 3: VT = T^T (fp16 -> fp16) ----------------
__global__ void k_vt() {
    __shared__ __half ts[32][34];
    int h = blockIdx.z, fb = blockIdx.y << 5, jt = blockIdx.x << 5;
    int tx = threadIdx.x & 31, ty = threadIdx.x >> 5;
#pragma unroll
    for (int k = 0; k < 4; k++) {
        int j = jt + ty + k * 8;
        ts[ty + k * 8][tx] = g_Th[(size_t)j * 256 + h * 128 + fb + tx];
    }
    __syncthreads();
#pragma unroll
    for (int k = 0; k < 4; k++) {
        int f = fb + ty + k * 8;
        g_VThi[((size_t)(h * 128 + f) << 13) + jt + tx] = ts[tx][ty + k * 8];
    }
}

// ---------------- kernel 4: adjacency -> bitmask ----------------
__global__ void k_adjbits(const int* __restrict__ adj) {
    int row = blockIdx.x, tid = threadIdx.x;
    const int4* a4 = (const int4*)(adj + (size_t)row * NN + tid * 32);
    uint32_t w = 0;
#pragma unroll
    for (int q = 0; q < 8; q++) {
        int4 v = a4[q];
        w |= (v.x != 0 ? 1u : 0u) << (q * 4 + 0);
        w |= (v.y != 0 ? 1u : 0u) << (q * 4 + 1);
        w |= (v.z != 0 ? 1u : 0u) << (q * 4 + 2);
        w |= (v.w != 0 ? 1u : 0u) << (q * 4 + 3);
    }
    g_adjbits[(size_t)row * 256 + tid] = w;
}

// ---------------- kernel 5: main — pipelined P-build + HMMA, split-K ----------------
// grid: (SPLITS, 2 heads, 64 i-tiles); block 256 = 8 warps (4 M x 2 N); 2 CTAs/SM
__global__ __launch_bounds__(256, 2) void k_gat_mma() {
    extern __shared__ char dsm[];
    uint32_t sb_raw = smem_u32(dsm);
    uint32_t sb = (sb_raw + 1023) & ~1023u;
    char* sp = dsm + (sb - sb_raw);

    int tid = threadIdx.x;
    int lane = tid & 31, wid = tid >> 5;
    int split = blockIdx.x, h = blockIdx.y, iTile = blockIdx.z;
    int iBase = iTile << 7;
    int jBase = split * JSPAN;

    // builder identity
    int bi = tid & 127, half = tid >> 7;
    int gi0 = (iBase + bi) * 2 + h;
    float e2i = g_EI2[gi0], e8i = g_EI8[gi0];
    float den = 0.f;
    int mrot = (bi >> 3) & 3;
    uint32_t pco = (uint32_t)(bi * 128 + half * 64);     // P row base (bytes)
    size_t arow = (size_t)(iBase + bi) * 256 + half;

    // V loader identity (4 float4 per thread per tile)
    int frow0 = tid >> 3, ch0 = tid & 7;                 // + c*32 rows per c

    // mma identity
    int wm = wid >> 1, wn = wid & 1;
    uint32_t aRow = (uint32_t)((wm * 32 + (lane & 15)) * 128 + (lane >> 4) * 16);
    uint32_t bRow = (uint32_t)((wn * 64 + ((lane >> 4) & 1) * 8 + (lane & 7)) * 128 +
                               ((lane >> 3) & 1) * 16);

    float acc[2][8][4];
#pragma unroll
    for (int a = 0; a < 2; a++)
#pragma unroll
        for (int b = 0; b < 8; b++)
#pragma unroll
            for (int c = 0; c < 4; c++) acc[a][b][c] = 0.f;

    float2* ejs = (float2*)(sp + EJ_OFF);
    float* dred = (float*)(sp + DR_OFF);
    const float4* vhi4 = (const float4*)g_VThi;

    // ---- prologue ----
    // EJ table for the whole split (2048 float2)
#pragma unroll
    for (int r = 0; r < 8; r++) {
        int u = tid + (r << 8);
        ejs[u] = g_EJ[(jBase + u) * 2 + h];
    }
    // V tile 0 direct to buf 0
#pragma unroll
    for (int c = 0; c < 4; c++) {
        int frow = frow0 + c * 32;
        int gidx = (h * 128 + frow) * 1024 + (jBase >> 3) + ch0;
        *(float4*)(sp + BH_OFF + swz((uint32_t)(frow * 128 + ch0 * 16))) = vhi4[gidx];
    }
    uint32_t word0 = g_adjbits[arow + ((uint32_t)jBase >> 5)];
    __syncthreads();   // EJ ready

    // build P tile 0 into buf 0
#pragma unroll
    for (int mm = 0; mm < 16; mm++) {
        int m = (mm + mrot * 4) & 15;
        int jj = half * 32 + 2 * m;
        float4 ev = *(const float4*)&ejs[jj];        // (e2x, e8x, e2y, e8y)
        float w0 = (e2i * ev.x) * fmaxf(e8i * ev.y, 1.f);
        float w1 = (e2i * ev.z) * fmaxf(e8i * ev.w, 1.f);
        w0 = ((word0 >> (2 * m)) & 1u) ? w0 : 0.f;
        w1 = ((word0 >> (2 * m + 1)) & 1u) ? w1 : 0.f;
        den += w0 + w1;
        *(__half2*)(sp + AH_OFF + swz(pco + 4 * m)) = __floats2half2_rn(w0, w1);
    }
    __syncthreads();   // P0 + V0 ready

    // ---- main loop: 1 barrier per tile ----
    for (int t = 0; t < TILES; t++) {
        uint32_t bb = (uint32_t)(t & 1) << 14;      // 16384-byte buffer stride
        uint32_t bn = bb ^ 16384u;

        // early: issue V(t+1) loads into regs + adjacency word
        float4 vr[4];
        uint32_t word;
        if (t + 1 < TILES) {
            int jt1 = jBase + (t + 1) * KT;
#pragma unroll
            for (int c = 0; c < 4; c++) {
                int frow = frow0 + c * 32;
                vr[c] = vhi4[(h * 128 + frow) * 1024 + (jt1 >> 3) + ch0];
            }
            word = g_adjbits[arow + ((uint32_t)jt1 >> 5)];
        }

        // MMA(t) from buffer bb
#pragma unroll
        for (int ks = 0; ks < 4; ks++) {
            uint32_t ah[2][4];
#pragma unroll
            for (int mi = 0; mi < 2; mi++)
                ldmx4(ah[mi], sb + AH_OFF + bb + swz(aRow + mi * 2048 + ks * 32));
#pragma unroll
            for (int nb = 0; nb < 4; nb++) {
                uint32_t bh4[4];
                ldmx4(bh4, sb + BH_OFF + bb + swz(bRow + nb * 2048 + ks * 32));
#pragma unroll
                for (int mi = 0; mi < 2; mi++) {
                    mma16816(acc[mi][2 * nb + 0], ah[mi], &bh4[0]);
                    mma16816(acc[mi][2 * nb + 1], ah[mi], &bh4[2]);
                }
            }
        }

        // produce tile t+1 into buffer bn
        if (t + 1 < TILES) {
            int ej0 = (t + 1) * KT + half * 32;
#pragma unroll
            for (int mm = 0; mm < 16; mm++) {
                int m = (mm + mrot * 4) & 15;
                float4 ev = *(const float4*)&ejs[ej0 + 2 * m];
                float w0 = (e2i * ev.x) * fmaxf(e8i * ev.y, 1.f);
                float w1 = (e2i * ev.z) * fmaxf(e8i * ev.w, 1.f);
                w0 = ((word >> (2 * m)) & 1u) ? w0 : 0.f;
                w1 = ((word >> (2 * m + 1)) & 1u) ? w1 : 0.f;
                den += w0 + w1;
                *(__half2*)(sp + AH_OFF + bn + swz(pco + 4 * m)) = __floats2half2_rn(w0, w1);
            }
#pragma unroll
            for (int c = 0; c < 4; c++) {
                int frow = frow0 + c * 32;
                *(float4*)(sp + BH_OFF + bn + swz((uint32_t)(frow * 128 + ch0 * 16))) = vr[c];
            }
        }
        __syncthreads();
    }

    // denominator reduce + store
    dred[tid] = den;
    __syncthreads();
    if (tid < 128)
        g_den[((size_t)split * NN + iBase + tid) * 2 + h] = dred[tid] + dred[tid + 128];

    // numerator stores
#pragma unroll
    for (int mi = 0; mi < 2; mi++)
#pragma unroll
        for (int nb8 = 0; nb8 < 8; nb8++) {
            int i0 = iBase + wm * 32 + mi * 16 + (lane >> 2);
            int f0 = wn * 64 + nb8 * 8 + (lane & 3) * 2;
            size_t b0 = ((size_t)(split * NN + i0) * 2 + h) * 128 + f0;
            *(float2*)&g_num[b0] = make_float2(acc[mi][nb8][0], acc[mi][nb8][1]);
            *(float2*)&g_num[b0 + 2048] = make_float2(acc[mi][nb8][2], acc[mi][nb8][3]);
        }
}

// ---------------- kernel 6: combine splits + normalize + head mean ----------------
__global__ void k_combine(float* __restrict__ out) {
    int idx = blockIdx.x * 256 + threadIdx.x;   // 1M
    int i = idx >> 7, f = idx & 127;
    float r = 0.f;
#pragma unroll
    for (int h = 0; h < 2; h++) {
        float n = 0.f, d = 0.f;
#pragma unroll
        for (int s = 0; s < SPLITS; s++) {
            n += g_num[(((size_t)s * NN + i) * 2 + h) * 128 + f];
            d += g_den[((size_t)s * NN + i) * 2 + h];
        }
        r += (d > 0.f) ? n / d : 0.f;
    }
    out[idx] = 0.5f * r;
}

// ---------------- launch ----------------
extern "C" void kernel_launch(void* const* d_in, const int* in_sizes, int n_in,
                              void* d_out, int out_size) {
    const float* features = (const float*)d_in[0];
    const int*   adjacency = (const int*)d_in[1];
    const float* W = (const float*)d_in[2];
    const float* attn_src = (const float*)d_in[3];
    const float* attn_dst = (const float*)d_in[4];
    float* out = (float*)d_out;

    cudaFuncSetAttribute(k_gat_mma, cudaFuncAttributeMaxDynamicSharedMemorySize, SMEM_DYN);

    k_prep<<<1, 256>>>(W, attn_src, attn_dst);
    k_wh<<<64, 256>>>(W);
    k_xh<<<2048, 256>>>(features);
    k_scores_x<<<NN / 8, 256>>>(features);
    k_gemm_h<<<dim3(64, 2), 256>>>();
    k_vt<<<dim3(NN / 32, 4, 2), 256>>>();
    k_adjbits<<<NN, 256>>>(adjacency);
    k_gat_mma<<<dim3(SPLITS, 2, 64), 256, SMEM_DYN>>>();
    k_combine<<<NN * OD / 256, 256>>>(out);
}

// round 17
// speedup vs baseline: 1.0627x; 1.0191x over previous
#include <cuda_runtime.h>
#include <cuda_bf16.h>
#include <cuda_fp16.h>
#include <cstdint>
#include <cstddef>

#define NN 8192
#define IND 256
#define OD 128
#define SPLITS 4
#define JSPAN (NN / SPLITS)      // 2048
#define KT 64                    // j per tile
#define TILES (JSPAN / KT)       // 32

// smem byte offsets (main kernel)
#define AH_OFF 0                 // P [2 buf][128 i][64 j] fp16 : 2 x 16 KB
#define BH_OFF 32768             // V [2 buf][128 f][64 j] fp16 : 2 x 16 KB
#define EJ_OFF 65536             // float2[2048] : 16 KB
#define DR_OFF 81920             // 256 floats (den reduce)
#define SMEM_USED (81920 + 1024)
#define SMEM_DYN (SMEM_USED + 1024)   // + alignment pad

// ---------------- device scratch ----------------
__device__ float g_U[4 * 256];           // u vectors: [src h0, src h1, dst h0, dst h1]
__device__ __half g_Xh[NN * IND];        // X in fp16
__device__ __half g_Wh[256 * 256];       // W in fp16
__device__ __half g_Th[NN * 256];        // T in fp16 (row-major)
__device__ float g_EI2[NN * 2];          // exp(0.2 s)
__device__ float g_EI8[NN * 2];          // exp(0.8 s)
__device__ float2 g_EJ[NN * 2];          // (exp(0.2 d), exp(0.8 d))
__device__ __half g_VThi[2 * 128 * NN];
__device__ uint32_t g_adjbits[(size_t)NN * (NN / 32)];   // 8 MB
__device__ float g_num[(size_t)SPLITS * NN * 2 * 128];   // 32 MB
__device__ float g_den[SPLITS * NN * 2];

// ---------------- helpers ----------------
__device__ __forceinline__ uint32_t smem_u32(const void* p) {
    uint32_t a;
    asm("{ .reg .u64 t; cvta.to.shared.u64 t, %1; cvt.u32.u64 %0, t; }" : "=r"(a) : "l"(p));
    return a;
}
__device__ __forceinline__ uint32_t swz(uint32_t x) { return x ^ ((x >> 3) & 0x70); }

__device__ __forceinline__ void ldmx4(uint32_t* r, uint32_t addr) {
    asm volatile("ldmatrix.sync.aligned.m8n8.x4.shared.b16 {%0,%1,%2,%3}, [%4];"
                 : "=r"(r[0]), "=r"(r[1]), "=r"(r[2]), "=r"(r[3]) : "r"(addr));
}
__device__ __forceinline__ void mma16816(float* c, const uint32_t* a, const uint32_t* b) {
    asm volatile("mma.sync.aligned.m16n8k16.row.col.f32.f16.f16.f32 "
                 "{%0,%1,%2,%3}, {%4,%5,%6,%7}, {%8,%9}, {%0,%1,%2,%3};"
                 : "+f"(c[0]), "+f"(c[1]), "+f"(c[2]), "+f"(c[3])
                 : "r"(a[0]), "r"(a[1]), "r"(a[2]), "r"(a[3]), "r"(b[0]), "r"(b[1]));
}

// ---------------- kernel 0a: u = attn @ W (per head, src/dst), fp32 exact ----------------
__global__ void k_prep(const float* __restrict__ W,
                       const float* __restrict__ asrc, const float* __restrict__ adst) {
    __shared__ float sa[256], sd[256];
    int k = threadIdx.x;
    sa[k] = asrc[k]; sd[k] = adst[k];
    __syncthreads();
    float us0 = 0.f, us1 = 0.f, ud0 = 0.f, ud1 = 0.f;
#pragma unroll 4
    for (int o = 0; o < 128; o++) {
        float w0 = W[o * 256 + k];
        float w1 = W[(128 + o) * 256 + k];
        us0 += sa[o] * w0;       ud0 += sd[o] * w0;
        us1 += sa[128 + o] * w1; ud1 += sd[128 + o] * w1;
    }
    g_U[0 * 256 + k] = us0; g_U[1 * 256 + k] = us1;
    g_U[2 * 256 + k] = ud0; g_U[3 * 256 + k] = ud1;
}

// ---------------- kernel 0b: W -> fp16 ----------------
__global__ void k_wh(const float* __restrict__ W) {
    int idx = blockIdx.x * 256 + threadIdx.x;    // 16384 float4
    float4 v = ((const float4*)W)[idx];
    __half2 a = __floats2half2_rn(v.x, v.y), b = __floats2half2_rn(v.z, v.w);
    ((uint2*)g_Wh)[idx] = make_uint2(*(uint32_t*)&a, *(uint32_t*)&b);
}

// ---------------- kernel 1: fused X->fp16 + scores (exact fp32) + exps ----------------
// warp per row: lane holds floats [lane*8, lane*8+8)
__global__ void k_xh_scores(const float* __restrict__ X) {
    __shared__ float4 su[256];                   // 4 u vectors x 64 float4
    int tid = threadIdx.x;
    su[tid] = ((const float4*)g_U)[tid];
    __syncthreads();
    int warp = blockIdx.x * 8 + (tid >> 5);
    int lane = tid & 31;
    const float4* X4 = (const float4*)X;
    float4 x0 = X4[(size_t)warp * 64 + lane * 2];
    float4 x1 = X4[(size_t)warp * 64 + lane * 2 + 1];

    // fp16 conversion + store (coalesced 16B per lane)
    __half2 a0 = __floats2half2_rn(x0.x, x0.y), b0 = __floats2half2_rn(x0.z, x0.w);
    __half2 a1 = __floats2half2_rn(x1.x, x1.y), b1 = __floats2half2_rn(x1.z, x1.w);
    ((uint4*)g_Xh)[(size_t)warp * 32 + lane] =
        make_uint4(*(uint32_t*)&a0, *(uint32_t*)&b0, *(uint32_t*)&a1, *(uint32_t*)&b1);

    float r[4];
#pragma unroll
    for (int v = 0; v < 4; v++) {
        float4 u0 = su[v * 64 + lane * 2];
        float4 u1 = su[v * 64 + lane * 2 + 1];
        r[v] = x0.x * u0.x + x0.y * u0.y + x0.z * u0.z + x0.w * u0.w +
               x1.x * u1.x + x1.y * u1.y + x1.z * u1.z + x1.w * u1.w;
    }
#pragma unroll
    for (int off = 16; off; off >>= 1)
#pragma unroll
        for (int v = 0; v < 4; v++)
            r[v] += __shfl_xor_sync(0xFFFFFFFFu, r[v], off);
    if (lane == 0) {
        g_EI2[warp * 2 + 0] = __expf(0.2f * r[0]);
        g_EI2[warp * 2 + 1] = __expf(0.2f * r[1]);
        g_EI8[warp * 2 + 0] = __expf(0.8f * r[0]);
        g_EI8[warp * 2 + 1] = __expf(0.8f * r[1]);
        g_EJ[warp * 2 + 0] = make_float2(__expf(0.2f * r[2]), __expf(0.8f * r[2]));
        g_EJ[warp * 2 + 1] = make_float2(__expf(0.2f * r[3]), __expf(0.8f * r[3]));
    }
}

// ---------------- kernel 2: T = X @ W^T via HMMA (fp16 in, fp16 out) ----------------
__global__ __launch_bounds__(256, 2) void k_gemm_h() {
    __shared__ __half At[128 * 64];              // 16 KB, SW128 rows of 128B
    __shared__ __half Bt[128 * 64];              // 16 KB
    uint32_t sbA = smem_u32(At), sbB = smem_u32(Bt);

    int tid = threadIdx.x;
    int lane = tid & 31, wid = tid >> 5;
    int mBase = blockIdx.x << 7, nBase = blockIdx.y << 7;

    int frow0 = tid >> 3, ch0 = tid & 7;
    int wm = wid >> 1, wn = wid & 1;
    uint32_t aRow = (uint32_t)((wm * 32 + (lane & 15)) * 128 + (lane >> 4) * 16);
    uint32_t bRow = (uint32_t)((wn * 64 + ((lane >> 4) & 1) * 8 + (lane & 7)) * 128 +
                               ((lane >> 3) & 1) * 16);

    float acc[2][8][4];
#pragma unroll
    for (int a = 0; a < 2; a++)
#pragma unroll
        for (int b = 0; b < 8; b++)
#pragma unroll
            for (int c = 0; c < 4; c++) acc[a][b][c] = 0.f;

    const float4* X4 = (const float4*)g_Xh;
    const float4* W4 = (const float4*)g_Wh;

    for (int kt = 0; kt < 4; kt++) {
        int kq = kt * 8;
#pragma unroll
        for (int c = 0; c < 4; c++) {
            int frow = frow0 + c * 32;
            uint32_t so = swz((uint32_t)(frow * 128 + ch0 * 16));
            *(float4*)((char*)At + so) = X4[(size_t)(mBase + frow) * 32 + kq + ch0];
            *(float4*)((char*)Bt + so) = W4[(size_t)(nBase + frow) * 32 + kq + ch0];
        }
        __syncthreads();
#pragma unroll
        for (int ks = 0; ks < 4; ks++) {
            uint32_t ah[2][4];
#pragma unroll
            for (int mi = 0; mi < 2; mi++)
                ldmx4(ah[mi], sbA + swz(aRow + mi * 2048 + ks * 32));
#pragma unroll
            for (int nb = 0; nb < 4; nb++) {
                uint32_t bh4[4];
                ldmx4(bh4, sbB + swz(bRow + nb * 2048 + ks * 32));
#pragma unroll
                for (int mi = 0; mi < 2; mi++) {
                    mma16816(acc[mi][2 * nb + 0], ah[mi], &bh4[0]);
                    mma16816(acc[mi][2 * nb + 1], ah[mi], &bh4[2]);
                }
            }
        }
        __syncthreads();
    }

#pragma unroll
    for (int mi = 0; mi < 2; mi++)
#pragma unroll
        for (int nb8 = 0; nb8 < 8; nb8++) {
            int i0 = mBase + wm * 32 + mi * 16 + (lane >> 2);
            int f0 = nBase + wn * 64 + nb8 * 8 + (lane & 3) * 2;
            __half2 lo = __floats2half2_rn(acc[mi][nb8][0], acc[mi][nb8][1]);
            __half2 hi = __floats2half2_rn(acc[mi][nb8][2], acc[mi][nb8][3]);
            *(__half2*)&g_Th[(size_t)i0 * 256 + f0] = lo;
            *(__half2*)&g_Th[(size_t)(i0 + 8) * 256 + f0] = hi;
        }
}

// ---------------- kernel 3: VT = T^T (fp16 -> fp16) ----------------
__global__ void k_vt() {
    __shared__ __half ts[32][34];
    int h = blockIdx.z, fb = blockIdx.y << 5, jt = blockIdx.x << 5;
    int tx = threadIdx.x & 31, ty = threadIdx.x >> 5;
#pragma unroll
    for (int k = 0; k < 4; k++) {
        int j = jt + ty + k * 8;
        ts[ty + k * 8][tx] = g_Th[(size_t)j * 256 + h * 128 + fb + tx];
    }
    __syncthreads();
#pragma unroll
    for (int k = 0; k < 4; k++) {
        int f = fb + ty + k * 8;
        g_VThi[((size_t)(h * 128 + f) << 13) + jt + tx] = ts[tx][ty + k * 8];
    }
}

// ---------------- kernel 4: adjacency -> bitmask ----------------
__global__ void k_adjbits(const int* __restrict__ adj) {
    int row = blockIdx.x, tid = threadIdx.x;
    const int4* a4 = (const int4*)(adj + (size_t)row * NN + tid * 32);
    uint32_t w = 0;
#pragma unroll
    for (int q = 0; q < 8; q++) {
        int4 v = a4[q];
        w |= (v.x != 0 ? 1u : 0u) << (q * 4 + 0);
        w |= (v.y != 0 ? 1u : 0u) << (q * 4 + 1);
        w |= (v.z != 0 ? 1u : 0u) << (q * 4 + 2);
        w |= (v.w != 0 ? 1u : 0u) << (q * 4 + 3);
    }
    g_adjbits[(size_t)row * 256 + tid] = w;
}

// ---------------- kernel 5: main — pipelined P-build + HMMA, split-K ----------------
__global__ __launch_bounds__(256, 2) void k_gat_mma() {
    extern __shared__ char dsm[];
    uint32_t sb_raw = smem_u32(dsm);
    uint32_t sb = (sb_raw + 1023) & ~1023u;
    char* sp = dsm + (sb - sb_raw);

    int tid = threadIdx.x;
    int lane = tid & 31, wid = tid >> 5;
    int split = blockIdx.x, h = blockIdx.y, iTile = blockIdx.z;
    int iBase = iTile << 7;
    int jBase = split * JSPAN;

    int bi = tid & 127, half = tid >> 7;
    int gi0 = (iBase + bi) * 2 + h;
    float e2i = g_EI2[gi0], e8i = g_EI8[gi0];
    float den = 0.f;
    int mrot = (bi >> 3) & 3;
    uint32_t pco = (uint32_t)(bi * 128 + half * 64);
    size_t arow = (size_t)(iBase + bi) * 256 + half;

    int frow0 = tid >> 3, ch0 = tid & 7;

    int wm = wid >> 1, wn = wid & 1;
    uint32_t aRow = (uint32_t)((wm * 32 + (lane & 15)) * 128 + (lane >> 4) * 16);
    uint32_t bRow = (uint32_t)((wn * 64 + ((lane >> 4) & 1) * 8 + (lane & 7)) * 128 +
                               ((lane >> 3) & 1) * 16);

    float acc[2][8][4];
#pragma unroll
    for (int a = 0; a < 2; a++)
#pragma unroll
        for (int b = 0; b < 8; b++)
#pragma unroll
            for (int c = 0; c < 4; c++) acc[a][b][c] = 0.f;

    float2* ejs = (float2*)(sp + EJ_OFF);
    float* dred = (float*)(sp + DR_OFF);
    const float4* vhi4 = (const float4*)g_VThi;

#pragma unroll
    for (int r = 0; r < 8; r++) {
        int u = tid + (r << 8);
        ejs[u] = g_EJ[(jBase + u) * 2 + h];
    }
#pragma unroll
    for (int c = 0; c < 4; c++) {
        int frow = frow0 + c * 32;
        int gidx = (h * 128 + frow) * 1024 + (jBase >> 3) + ch0;
        *(float4*)(sp + BH_OFF + swz((uint32_t)(frow * 128 + ch0 * 16))) = vhi4[gidx];
    }
    uint32_t word0 = g_adjbits[arow + ((uint32_t)jBase >> 5)];
    __syncthreads();

#pragma unroll
    for (int mm = 0; mm < 16; mm++) {
        int m = (mm + mrot * 4) & 15;
        int jj = half * 32 + 2 * m;
        float4 ev = *(const float4*)&ejs[jj];
        float w0 = (e2i * ev.x) * fmaxf(e8i * ev.y, 1.f);
        float w1 = (e2i * ev.z) * fmaxf(e8i * ev.w, 1.f);
        w0 = ((word0 >> (2 * m)) & 1u) ? w0 : 0.f;
        w1 = ((word0 >> (2 * m + 1)) & 1u) ? w1 : 0.f;
        den += w0 + w1;
        *(__half2*)(sp + AH_OFF + swz(pco + 4 * m)) = __floats2half2_rn(w0, w1);
    }
    __syncthreads();

    for (int t = 0; t < TILES; t++) {
        uint32_t bb = (uint32_t)(t & 1) << 14;
        uint32_t bn = bb ^ 16384u;

        float4 vr[4];
        uint32_t word;
        if (t + 1 < TILES) {
            int jt1 = jBase + (t + 1) * KT;
#pragma unroll
            for (int c = 0; c < 4; c++) {
                int frow = frow0 + c * 32;
                vr[c] = vhi4[(h * 128 + frow) * 1024 + (jt1 >> 3) + ch0];
            }
            word = g_adjbits[arow + ((uint32_t)jt1 >> 5)];
        }

#pragma unroll
        for (int ks = 0; ks < 4; ks++) {
            uint32_t ah[2][4];
#pragma unroll
            for (int mi = 0; mi < 2; mi++)
                ldmx4(ah[mi], sb + AH_OFF + bb + swz(aRow + mi * 2048 + ks * 32));
#pragma unroll
            for (int nb = 0; nb < 4; nb++) {
                uint32_t bh4[4];
                ldmx4(bh4, sb + BH_OFF + bb + swz(bRow + nb * 2048 + ks * 32));
#pragma unroll
                for (int mi = 0; mi < 2; mi++) {
                    mma16816(acc[mi][2 * nb + 0], ah[mi], &bh4[0]);
                    mma16816(acc[mi][2 * nb + 1], ah[mi], &bh4[2]);
                }
            }
        }

        if (t + 1 < TILES) {
            int ej0 = (t + 1) * KT + half * 32;
#pragma unroll
            for (int mm = 0; mm < 16; mm++) {
                int m = (mm + mrot * 4) & 15;
                float4 ev = *(const float4*)&ejs[ej0 + 2 * m];
                float w0 = (e2i * ev.x) * fmaxf(e8i * ev.y, 1.f);
                float w1 = (e2i * ev.z) * fmaxf(e8i * ev.w, 1.f);
                w0 = ((word >> (2 * m)) & 1u) ? w0 : 0.f;
                w1 = ((word >> (2 * m + 1)) & 1u) ? w1 : 0.f;
                den += w0 + w1;
                *(__half2*)(sp + AH_OFF + bn + swz(pco + 4 * m)) = __floats2half2_rn(w0, w1);
            }
#pragma unroll
            for (int c = 0; c < 4; c++) {
                int frow = frow0 + c * 32;
                *(float4*)(sp + BH_OFF + bn + swz((uint32_t)(frow * 128 + ch0 * 16))) = vr[c];
            }
        }
        __syncthreads();
    }

    dred[tid] = den;
    __syncthreads();
    if (tid < 128)
        g_den[((size_t)split * NN + iBase + tid) * 2 + h] = dred[tid] + dred[tid + 128];

#pragma unroll
    for (int mi = 0; mi < 2; mi++)
#pragma unroll
        for (int nb8 = 0; nb8 < 8; nb8++) {
            int i0 = iBase + wm * 32 + mi * 16 + (lane >> 2);
            int f0 = wn * 64 + nb8 * 8 + (lane & 3) * 2;
            size_t b0 = ((size_t)(split * NN + i0) * 2 + h) * 128 + f0;
            *(float2*)&g_num[b0] = make_float2(acc[mi][nb8][0], acc[mi][nb8][1]);
            *(float2*)&g_num[b0 + 2048] = make_float2(acc[mi][nb8][2], acc[mi][nb8][3]);
        }
}

// ---------------- kernel 6: combine splits + normalize + head mean ----------------
__global__ void k_combine(float* __restrict__ out) {
    int idx = blockIdx.x * 256 + threadIdx.x;   // 1M
    int i = idx >> 7, f = idx & 127;
    float r = 0.f;
#pragma unroll
    for (int h = 0; h < 2; h++) {
        float n = 0.f, d = 0.f;
#pragma unroll
        for (int s = 0; s < SPLITS; s++) {
            n += g_num[(((size_t)s * NN + i) * 2 + h) * 128 + f];
            d += g_den[((size_t)s * NN + i) * 2 + h];
        }
        r += (d > 0.f) ? n / d : 0.f;
    }
    out[idx] = 0.5f * r;
}

// ---------------- launch ----------------
extern "C" void kernel_launch(void* const* d_in, const int* in_sizes, int n_in,
                              void* d_out, int out_size) {
    const float* features = (const float*)d_in[0];
    const int*   adjacency = (const int*)d_in[1];
    const float* W = (const float*)d_in[2];
    const float* attn_src = (const float*)d_in[3];
    const float* attn_dst = (const float*)d_in[4];
    float* out = (float*)d_out;

    static cudaStream_t s2 = nullptr;
    static cudaEvent_t evF = nullptr, evJ = nullptr;
    if (s2 == nullptr) {
        cudaStreamCreate(&s2);
        cudaEventCreateWithFlags(&evF, cudaEventDisableTiming);
        cudaEventCreateWithFlags(&evJ, cudaEventDisableTiming);
    }

    cudaFuncSetAttribute(k_gat_mma, cudaFuncAttributeMaxDynamicSharedMemorySize, SMEM_DYN);

    // fork: adjacency bitmask build on side stream (DRAM-bound, overlaps compute chain)
    cudaEventRecord(evF, 0);
    cudaStreamWaitEvent(s2, evF, 0);
    k_adjbits<<<NN, 256, 0, s2>>>(adjacency);
    cudaEventRecord(evJ, s2);

    // main-stream compute chain
    k_prep<<<1, 256>>>(W, attn_src, attn_dst);
    k_wh<<<64, 256>>>(W);
    k_xh_scores<<<NN / 8, 256>>>(features);
    k_gemm_h<<<dim3(64, 2), 256>>>();
    k_vt<<<dim3(NN / 32, 4, 2), 256>>>();

    // join: main kernel needs adjbits
    cudaStreamWaitEvent(0, evJ, 0);
    k_gat_mma<<<dim3(SPLITS, 2, 64), 256, SMEM_DYN>>>();
    k_combine<<<NN * OD / 256, 256>>>(out);
}